// round 6
// baseline (speedup 1.0000x reference)
#include <cuda_runtime.h>

#define BN 16
#define CN 1024
#define TN 16
#define PN 360          // H*W
#define KN 120
#define OUTROWS 482     // 1 + 120 + 1 + 360
#define CT 64           // K1 tile: c extent
#define PT 180          // K1 tile: p extent (2 tiles cover PN exactly)
#define NCT (CN / CT)   // 16 c-tiles
#define PLANE (TN * PN) // 5760 floats per (b,c) plane
#define STRIDE (2 * PT + 1)   // 361 floats per smem row
#define K1_THREADS 320
#define K1_SMEM ((CT * STRIDE + CT) * 4)   // tile + scls, bytes

// K3 tiling (round-5 proven)
#define CT3 64
#define PT3 64
#define NPT3 6

// scratch (no allocations allowed)
__device__ float g_partial[BN][NCT][PN];
__device__ int   g_rank[BN][PN];

// ---------------------------------------------------------------------------
// K1 (fused, long-span): block = (b, c-tile 64, p-half 180).
// Reads two contiguous 720B spans (frame 0 + frame 1) per c-plane -> smem.
//   - scores: g_partial[b][ct][p] = sum_{c in tile} cls[b,0,c] * x0[c,p]
//   - frame-1 out: out[b, 122+p, c] = x1[c,p]   (STG.128 along c)
// 18 exact-trip LDG.128 per thread; no bounds predicates anywhere.
// ---------------------------------------------------------------------------
__global__ void __launch_bounds__(K1_THREADS, 1)
fused_kernel(const float* __restrict__ x, const float* __restrict__ cls,
             float* __restrict__ out) {
    extern __shared__ float sm[];
    float* tile = sm;                    // [CT][STRIDE]: cols 0..179 f0, 180..359 f1
    float* scls = sm + CT * STRIDE;      // [CT]
    const int tid = threadIdx.x;
    const int b  = blockIdx.z;
    const int c0 = blockIdx.y * CT;
    const int p0 = blockIdx.x * PT;
    const float* xplane = x + ((size_t)b * CN + c0) * PLANE;

    if (tid < CT) scls[tid] = cls[(size_t)b * TN * CN + c0 + tid];

    // load: 64 c-rows x 90 quads (2 frames x 45), 5760 quads / 320 = 18 iters
#pragma unroll
    for (int it = 0; it < (CT * 2 * (PT / 4)) / K1_THREADS; ++it) {
        int idx = tid + it * K1_THREADS;
        int cc = idx / (2 * (PT / 4));
        int q  = idx % (2 * (PT / 4));
        int f  = q / (PT / 4);
        int pq = q % (PT / 4);
        float4 v = *(const float4*)(xplane + (size_t)cc * PLANE + f * PN + p0 + 4 * pq);
        float* dst = tile + cc * STRIDE + f * PT + 4 * pq;
        dst[0] = v.x; dst[1] = v.y; dst[2] = v.z; dst[3] = v.w;
    }
    __syncthreads();

    // scores from frame-0 half (conflict-free: consecutive pl -> consecutive floats)
    if (tid < PT) {
        float a0 = 0.f, a1 = 0.f;
#pragma unroll
        for (int c = 0; c < CT; c += 2) {
            a0 = fmaf(scls[c],     tile[c * STRIDE + tid],       a0);
            a1 = fmaf(scls[c + 1], tile[(c + 1) * STRIDE + tid], a1);
        }
        g_partial[b][blockIdx.y][p0 + tid] = a0 + a1;
    }

    // frame-1 transposed store: 180 p-rows x 16 c-quads = 2880 / 320 = 9 iters
#pragma unroll
    for (int it = 0; it < (PT * (CT / 4)) / K1_THREADS; ++it) {
        int idx = tid + it * K1_THREADS;
        int pl = idx >> 4, cq = idx & 15;
        float4 v;
        v.x = tile[(4 * cq + 0) * STRIDE + PT + pl];
        v.y = tile[(4 * cq + 1) * STRIDE + PT + pl];
        v.z = tile[(4 * cq + 2) * STRIDE + PT + pl];
        v.w = tile[(4 * cq + 3) * STRIDE + PT + pl];
        *(float4*)(out + ((size_t)b * OUTROWS + 122 + p0 + pl) * CN + c0 + 4 * cq) = v;
    }
}

// ---------------------------------------------------------------------------
// K2: reduce 16 partials -> score, exact stable descending rank (matches jax
// top_k tie-breaking: #greater + #equal-with-smaller-index), copy cls rows.
// Monotone transforms (/sqrt(c), softmax, /frame_max) cannot change ordering.
// ---------------------------------------------------------------------------
__global__ void __launch_bounds__(384)
rank_kernel(const float* __restrict__ cls, float* __restrict__ out) {
    const int b = blockIdx.x;
    const int p = threadIdx.x;
    __shared__ float s[PN];
    float v = 0.f;
    if (p < PN) {
#pragma unroll
        for (int k = 0; k < NCT; ++k) v += g_partial[b][k][p];
        s[p] = v;
    }
    __syncthreads();
    if (p < PN) {
        int cnt = 0;
#pragma unroll 8
        for (int q = 0; q < PN; ++q) {
            float sq = s[q];
            cnt += (sq > v) || (sq == v && q < p);
        }
        g_rank[b][p] = cnt;
    }
    if (threadIdx.x < 256) {
        const float4* c4 = (const float4*)(cls + (size_t)b * TN * CN);
        float4* o4 = (float4*)(out + (size_t)b * OUTROWS * CN);
        o4[threadIdx.x] = c4[threadIdx.x];                            // row 0
        o4[(size_t)121 * 256 + threadIdx.x] = c4[256 + threadIdx.x];  // row 121
    }
}

// ---------------------------------------------------------------------------
// K3: frame-0 scatter (round-5 proven).
//   out[b, 1+rank[p], c] = x[b,c,0,p]   for rank[p] < K
// ---------------------------------------------------------------------------
__global__ void __launch_bounds__(256)
scatter0_kernel(const float* __restrict__ x, float* __restrict__ out) {
    __shared__ float tile[PT3][CT3 + 1];
    __shared__ int   rk[PT3];
    const int tid = threadIdx.x;
    const int b  = blockIdx.z;
    const int c0 = blockIdx.y * CT3;
    const int p0 = blockIdx.x * PT3;
    const float* xplane = x + ((size_t)b * CN + c0) * PLANE;   // t = 0

    if (tid < PT3) {
        int p = p0 + tid;
        rk[tid] = (p < PN) ? g_rank[b][p] : KN;
    }

#pragma unroll
    for (int it = 0; it < (CT3 * (PT3 / 4)) / 256; ++it) {   // 4 iters
        int idx = tid + it * 256;
        int cc = idx >> 4, pq = idx & 15;
        int p = p0 + 4 * pq;
        if (p < PN) {
            float4 v = *(const float4*)(xplane + (size_t)cc * PLANE + p);
            tile[4 * pq + 0][cc] = v.x;
            tile[4 * pq + 1][cc] = v.y;
            tile[4 * pq + 2][cc] = v.z;
            tile[4 * pq + 3][cc] = v.w;
        }
    }
    __syncthreads();

#pragma unroll
    for (int it = 0; it < (PT3 * (CT3 / 4)) / 256; ++it) {   // 4 iters
        int idx = tid + it * 256;
        int pl = idx >> 4, cq = idx & 15;
        int r = rk[pl];
        if (r >= KN) continue;
        float4 v;
        v.x = tile[pl][4 * cq + 0];
        v.y = tile[pl][4 * cq + 1];
        v.z = tile[pl][4 * cq + 2];
        v.w = tile[pl][4 * cq + 3];
        *(float4*)(out + ((size_t)b * OUTROWS + 1 + r) * CN + c0 + 4 * cq) = v;
    }
}

extern "C" void kernel_launch(void* const* d_in, const int* in_sizes, int n_in,
                              void* d_out, int out_size) {
    const float* x   = (const float*)d_in[0];   // [16,1024,16,12,30] f32
    const float* cls = (const float*)d_in[1];   // [16,16,1024] f32
    float* out = (float*)d_out;                 // [16,482,1024] f32

    static int smem_set = 0;
    if (!smem_set) {
        cudaFuncSetAttribute(fused_kernel,
                             cudaFuncAttributeMaxDynamicSharedMemorySize, K1_SMEM);
        smem_set = 1;
    }

    fused_kernel<<<dim3(2, NCT, BN), K1_THREADS, K1_SMEM>>>(x, cls, out);
    rank_kernel<<<BN, 384>>>(cls, out);
    scatter0_kernel<<<dim3(NPT3, NCT, BN), 256>>>(x, out);
}

// round 7
// speedup vs baseline: 1.1179x; 1.1179x over previous
#include <cuda_runtime.h>

#define BN 16
#define CN 1024
#define TN 16
#define PN 360          // H*W
#define KN 120
#define OUTROWS 482     // 1 + 120 + 1 + 360
#define CT 64           // K1 tile: c extent
#define PT 64           // K1 tile: p extent
#define NCT (CN / CT)   // 16 c-tiles
#define NPT 6           // ceil(PN/PT)
#define PLANE (TN * PN) // 5760 floats per (b,c) plane

// scratch (no allocations allowed)
__device__ float g_partial[BN][NCT][PN];
__device__ int   g_sel[BN][KN];                 // sel[r] = p with rank r
__device__ float g_scratch[BN][PN][CN];         // frame-0 transposed tokens

// ---------------------------------------------------------------------------
// K1 (fused single pass over x) — round-5 proven geometry.
// block = (b, c-tile 64, p-tile 64); loads frame-0 + frame-1 spans to smem.
//   - partial scores:  g_partial[b][ct][p] = sum_{c in tile} cls[b,0,c]*x0
//   - frame-1 output:  out[b, 122+p, c] = x1        (STG.128, streaming)
//   - frame-0 scratch: scratch[b][p][c]  = x0        (STG.128, contiguous)
// ---------------------------------------------------------------------------
__global__ void __launch_bounds__(256)
fused_kernel(const float* __restrict__ x, const float* __restrict__ cls,
             float* __restrict__ out) {
    __shared__ float tile[2 * PT][CT + 1];   // [f*64 + p_local][cc]
    __shared__ float scls[CT];
    __shared__ float sacc[4][PT];
    const int tid = threadIdx.x;
    const int b  = blockIdx.z;
    const int c0 = blockIdx.y * CT;
    const int p0 = blockIdx.x * PT;
    const float* xplane = x + ((size_t)b * CN + c0) * PLANE;

    if (tid < CT) scls[tid] = cls[(size_t)b * TN * CN + c0 + tid];

    // load: 64 c-rows x 32 quads (2 frames x 16 p-quads), LDG.128
#pragma unroll
    for (int it = 0; it < (CT * 32) / 256; ++it) {      // 8 iters
        int idx = tid + it * 256;
        int cc = idx >> 5, q = idx & 31;
        int f = q >> 4, pq = q & 15;
        int p = p0 + 4 * pq;
        float4 v = make_float4(0.f, 0.f, 0.f, 0.f);
        if (p < PN)
            v = *(const float4*)(xplane + (size_t)cc * PLANE + f * PN + p);
        int r = f * PT + 4 * pq;
        tile[r + 0][cc] = v.x;
        tile[r + 1][cc] = v.y;
        tile[r + 2][cc] = v.z;
        tile[r + 3][cc] = v.w;
    }
    __syncthreads();

    // partial scores from frame-0 half (conflict-free: bank=(pl+c)%32)
    {
        int pl = tid & 63, csub = tid >> 6;
        float a = 0.f;
#pragma unroll
        for (int j = 0; j < 16; ++j) {
            int c = csub * 16 + j;
            a = fmaf(scls[c], tile[pl][c], a);
        }
        sacc[csub][pl] = a;
    }

    // frame-1 -> out (streaming) and frame-0 -> scratch: 64 p-rows x 16 c-quads each
#pragma unroll
    for (int it = 0; it < (PT * (CT / 4)) / 256; ++it) {   // 4 iters
        int idx = tid + it * 256;
        int pl = idx >> 4, cq = idx & 15;
        int p = p0 + pl;
        if (p < PN) {
            float4 v1;
            v1.x = tile[PT + pl][4 * cq + 0];
            v1.y = tile[PT + pl][4 * cq + 1];
            v1.z = tile[PT + pl][4 * cq + 2];
            v1.w = tile[PT + pl][4 * cq + 3];
            __stcs((float4*)(out + ((size_t)b * OUTROWS + 122 + p) * CN + c0 + 4 * cq), v1);

            float4 v0;
            v0.x = tile[pl][4 * cq + 0];
            v0.y = tile[pl][4 * cq + 1];
            v0.z = tile[pl][4 * cq + 2];
            v0.w = tile[pl][4 * cq + 3];
            *(float4*)(&g_scratch[b][p][c0 + 4 * cq]) = v0;
        }
    }
    __syncthreads();

    if (tid < PT) {
        int p = p0 + tid;
        if (p < PN)
            g_partial[b][blockIdx.y][p] =
                (sacc[0][tid] + sacc[1][tid]) + (sacc[2][tid] + sacc[3][tid]);
    }
}

// ---------------------------------------------------------------------------
// K2: reduce 16 partials -> score, exact stable descending rank (matches jax
// top_k tie-breaking: #greater + #equal-with-smaller-index), emit inverse
// selection sel[r] = p, copy the two cls rows. Monotone transforms
// (/sqrt(c), softmax, /frame_max) cannot change the ordering.
// ---------------------------------------------------------------------------
__global__ void __launch_bounds__(384)
rank_kernel(const float* __restrict__ cls, float* __restrict__ out) {
    const int b = blockIdx.x;
    const int p = threadIdx.x;
    __shared__ float s[PN];
    float v = 0.f;
    if (p < PN) {
#pragma unroll
        for (int k = 0; k < NCT; ++k) v += g_partial[b][k][p];
        s[p] = v;
    }
    __syncthreads();
    if (p < PN) {
        int cnt = 0;
#pragma unroll 8
        for (int q = 0; q < PN; ++q) {
            float sq = s[q];
            cnt += (sq > v) || (sq == v && q < p);
        }
        if (cnt < KN) g_sel[b][cnt] = p;     // ranks are a permutation: no races
    }
    // out[b,0,:] = cls[b,0,:]; out[b,121,:] = cls[b,1,:]  (float4)
    if (threadIdx.x < 256) {
        const float4* c4 = (const float4*)(cls + (size_t)b * TN * CN);
        float4* o4 = (float4*)(out + (size_t)b * OUTROWS * CN);
        o4[threadIdx.x] = c4[threadIdx.x];                            // row 0
        o4[(size_t)121 * 256 + threadIdx.x] = c4[256 + threadIdx.x];  // row 121
    }
}

// ---------------------------------------------------------------------------
// K3: trivial row gather. block = (b, r): out[b, 1+r, :] = scratch[b, sel[r], :]
// 4 KB contiguous copy per block; reads are L2-hot from K1's scratch writes.
// ---------------------------------------------------------------------------
__global__ void __launch_bounds__(256)
gather_kernel(float* __restrict__ out) {
    const int b = blockIdx.x / KN;
    const int r = blockIdx.x % KN;
    const int p = g_sel[b][r];
    const float4* src = (const float4*)(&g_scratch[b][p][0]);
    float4* dst = (float4*)(out + ((size_t)b * OUTROWS + 1 + r) * CN);
    __stcs(dst + threadIdx.x, src[threadIdx.x]);
}

extern "C" void kernel_launch(void* const* d_in, const int* in_sizes, int n_in,
                              void* d_out, int out_size) {
    const float* x   = (const float*)d_in[0];   // [16,1024,16,12,30] f32
    const float* cls = (const float*)d_in[1];   // [16,16,1024] f32
    float* out = (float*)d_out;                 // [16,482,1024] f32

    fused_kernel<<<dim3(NPT, NCT, BN), 256>>>(x, cls, out);
    rank_kernel<<<BN, 384>>>(cls, out);
    gather_kernel<<<BN * KN, 256>>>(out);
}

// round 8
// speedup vs baseline: 1.1965x; 1.0703x over previous
#include <cuda_runtime.h>

#define BN 16
#define CN 1024
#define TN 16
#define PN 360          // H*W
#define KN 120
#define OUTROWS 482     // 1 + 120 + 1 + 360
#define CT 64           // K1 tile: c extent
#define PT 64           // K1 tile: p extent
#define NCT (CN / CT)   // 16 c-tiles
#define NPT 6           // ceil(PN/PT)
#define PLANE (TN * PN) // 5760 floats per (b,c) plane
#define TS 68           // tile row stride (floats)

// scratch (no allocations allowed)
__device__ float g_partial[BN][NCT][PN];
__device__ int   g_rank[BN][PN];

// ---------------------------------------------------------------------------
// K1: single fused pass over x[b, :, 0:2, :].
// Warp split by lane: lanes 0-15 (f=0) FMA frame-0 quads into registers
// (no smem round trip); lanes 16-31 (f=1) STS.128 frame-1 quads into a
// [c][p]-layout tile. Then frame-1 transposed STG.128 to out, and the
// register partials reduce through tiny sacc.
// ---------------------------------------------------------------------------
__global__ void __launch_bounds__(256)
fused_kernel(const float* __restrict__ x, const float* __restrict__ cls,
             float* __restrict__ out) {
    __shared__ float tile[CT][TS];     // frame-1 only, [cc][pp]
    __shared__ float scls[CT];
    __shared__ float sacc[8][PT];
    const int tid = threadIdx.x;
    const int b  = blockIdx.z;
    const int c0 = blockIdx.y * CT;
    const int p0 = blockIdx.x * PT;
    const float* xplane = x + ((size_t)b * CN + c0) * PLANE;

    if (tid < CT) scls[tid] = cls[(size_t)b * TN * CN + c0 + tid];
    __syncthreads();

    const int q  = tid & 31;
    const int wg = tid >> 5;          // 8 warps
    const int f  = q >> 4;            // lane 0-15: frame 0, lane 16-31: frame 1
    const int pq = q & 15;
    const int p  = p0 + 4 * pq;
    const bool valid = (p < PN);

    float4 acc = make_float4(0.f, 0.f, 0.f, 0.f);
#pragma unroll
    for (int it = 0; it < 8; ++it) {               // cc = wg + it*8
        int cc = wg + it * 8;
        float4 v = make_float4(0.f, 0.f, 0.f, 0.f);
        if (valid)
            v = *(const float4*)(xplane + (size_t)cc * PLANE + f * PN + p);
        if (f == 0) {
            float s = scls[cc];                    // broadcast LDS
            acc.x = fmaf(s, v.x, acc.x);
            acc.y = fmaf(s, v.y, acc.y);
            acc.z = fmaf(s, v.z, acc.z);
            acc.w = fmaf(s, v.w, acc.w);
        } else {
            *(float4*)&tile[cc][4 * pq] = v;       // STS.128
        }
    }
    if (f == 0)
        *(float4*)&sacc[wg][4 * pq] = acc;         // STS.128
    __syncthreads();

    // reduce partials: 64 threads, 8 LDS each
    if (tid < PT) {
        int pp = p0 + tid;
        if (pp < PN) {
            float a = 0.f;
#pragma unroll
            for (int w = 0; w < 8; ++w) a += sacc[w][tid];
            g_partial[b][blockIdx.y][pp] = a;
        }
    }

    // frame-1 transposed store: 64 p-rows x 16 c-quads, STG.128 streaming
#pragma unroll
    for (int it = 0; it < 4; ++it) {
        int idx = tid + it * 256;
        int pl = idx >> 4, cq = idx & 15;
        int pp = p0 + pl;
        if (pp < PN) {
            float4 v;
            v.x = tile[4 * cq + 0][pl];
            v.y = tile[4 * cq + 1][pl];
            v.z = tile[4 * cq + 2][pl];
            v.w = tile[4 * cq + 3][pl];
            __stcs((float4*)(out + ((size_t)b * OUTROWS + 122 + pp) * CN + c0 + 4 * cq), v);
        }
    }
}

// ---------------------------------------------------------------------------
// K2: reduce 16 partials -> score, exact stable descending rank (matches jax
// top_k tie-breaking: #greater + #equal-with-smaller-index), copy cls rows.
// Monotone transforms (/sqrt(c), softmax, /frame_max) cannot change ordering.
// ---------------------------------------------------------------------------
__global__ void __launch_bounds__(384)
rank_kernel(const float* __restrict__ cls, float* __restrict__ out) {
    const int b = blockIdx.x;
    const int p = threadIdx.x;
    __shared__ float s[PN];
    float v = 0.f;
    if (p < PN) {
#pragma unroll
        for (int k = 0; k < NCT; ++k) v += g_partial[b][k][p];
        s[p] = v;
    }
    __syncthreads();
    if (p < PN) {
        int cnt = 0;
#pragma unroll 8
        for (int q = 0; q < PN; ++q) {
            float sq = s[q];
            cnt += (sq > v) || (sq == v && q < p);
        }
        g_rank[b][p] = cnt;
    }
    if (threadIdx.x < 256) {
        const float4* c4 = (const float4*)(cls + (size_t)b * TN * CN);
        float4* o4 = (float4*)(out + (size_t)b * OUTROWS * CN);
        o4[threadIdx.x] = c4[threadIdx.x];                            // row 0
        o4[(size_t)121 * 256 + threadIdx.x] = c4[256 + threadIdx.x];  // row 121
    }
}

// ---------------------------------------------------------------------------
// K3: frame-0 scatter (reads L2-resident after K1).
//   out[b, 1+rank[p], c] = x[b,c,0,p]   for rank[p] < K
// ---------------------------------------------------------------------------
__global__ void __launch_bounds__(256)
scatter0_kernel(const float* __restrict__ x, float* __restrict__ out) {
    __shared__ float tile[PT][CT + 1];
    __shared__ int   rk[PT];
    const int tid = threadIdx.x;
    const int b  = blockIdx.z;
    const int c0 = blockIdx.y * CT;
    const int p0 = blockIdx.x * PT;
    const float* xplane = x + ((size_t)b * CN + c0) * PLANE;   // t = 0

    if (tid < PT) {
        int p = p0 + tid;
        rk[tid] = (p < PN) ? g_rank[b][p] : KN;
    }

#pragma unroll
    for (int it = 0; it < 4; ++it) {
        int idx = tid + it * 256;
        int cc = idx >> 4, pq = idx & 15;
        int p = p0 + 4 * pq;
        if (p < PN) {
            float4 v = *(const float4*)(xplane + (size_t)cc * PLANE + p);
            tile[4 * pq + 0][cc] = v.x;
            tile[4 * pq + 1][cc] = v.y;
            tile[4 * pq + 2][cc] = v.z;
            tile[4 * pq + 3][cc] = v.w;
        }
    }
    __syncthreads();

#pragma unroll
    for (int it = 0; it < 4; ++it) {
        int idx = tid + it * 256;
        int pl = idx >> 4, cq = idx & 15;
        int r = rk[pl];
        if (r >= KN) continue;
        float4 v;
        v.x = tile[pl][4 * cq + 0];
        v.y = tile[pl][4 * cq + 1];
        v.z = tile[pl][4 * cq + 2];
        v.w = tile[pl][4 * cq + 3];
        __stcs((float4*)(out + ((size_t)b * OUTROWS + 1 + r) * CN + c0 + 4 * cq), v);
    }
}

extern "C" void kernel_launch(void* const* d_in, const int* in_sizes, int n_in,
                              void* d_out, int out_size) {
    const float* x   = (const float*)d_in[0];   // [16,1024,16,12,30] f32
    const float* cls = (const float*)d_in[1];   // [16,16,1024] f32
    float* out = (float*)d_out;                 // [16,482,1024] f32

    fused_kernel<<<dim3(NPT, NCT, BN), 256>>>(x, cls, out);
    rank_kernel<<<BN, 384>>>(cls, out);
    scatter0_kernel<<<dim3(NPT, NCT, BN), 256>>>(x, out);
}